// round 7
// baseline (speedup 1.0000x reference)
#include <cuda_runtime.h>

namespace {

constexpr int NT = 128;  // batches per block

struct X {
    float r0, r1, r2, r3, r4, r5, r6, r7, r8;  // 3x3 rotation, row-major
    float tx, ty, tz;                           // translation
};

// Local transform from (unnormalized) quat (w,x,y,z) + position.
// s = 2/|q|^2 — identical to normalize-then-rotmat.
__device__ __forceinline__ X make_local(float4 q, float px, float py, float pz) {
    X o;
    float n = q.x * q.x + q.y * q.y + q.z * q.z + q.w * q.w;
    float s = __fdividef(2.0f, n);
    // q.x=w q.y=x q.z=y q.w=z (reference order)
    float x2 = q.y * s, y2 = q.z * s, z2 = q.w * s;
    float xx = q.y * x2, yy = q.z * y2, zz = q.w * z2;
    float xy = q.y * y2, yz = q.z * z2, xz = q.y * z2;
    float wx = q.x * x2, wy = q.x * y2, wz = q.x * z2;
    o.r0 = 1.0f - (yy + zz); o.r1 = xy - wz;          o.r2 = xz + wy;
    o.r3 = xy + wz;          o.r4 = 1.0f - (xx + zz); o.r5 = yz - wx;
    o.r6 = xz - wy;          o.r7 = yz + wx;          o.r8 = 1.0f - (xx + yy);
    o.tx = px; o.ty = py; o.tz = pz;
    return o;
}

// Affine compose: c = a ∘ b (a = parent global, b = child local)
__device__ __forceinline__ X xmul(const X& a, const X& b) {
    X c;
    c.r0 = a.r0 * b.r0 + a.r1 * b.r3 + a.r2 * b.r6;
    c.r1 = a.r0 * b.r1 + a.r1 * b.r4 + a.r2 * b.r7;
    c.r2 = a.r0 * b.r2 + a.r1 * b.r5 + a.r2 * b.r8;
    c.r3 = a.r3 * b.r0 + a.r4 * b.r3 + a.r5 * b.r6;
    c.r4 = a.r3 * b.r1 + a.r4 * b.r4 + a.r5 * b.r7;
    c.r5 = a.r3 * b.r2 + a.r4 * b.r5 + a.r5 * b.r8;
    c.r6 = a.r6 * b.r0 + a.r7 * b.r3 + a.r8 * b.r6;
    c.r7 = a.r6 * b.r1 + a.r7 * b.r4 + a.r8 * b.r7;
    c.r8 = a.r6 * b.r2 + a.r7 * b.r5 + a.r8 * b.r8;
    c.tx = a.r0 * b.tx + a.r1 * b.ty + a.r2 * b.tz + a.tx;
    c.ty = a.r3 * b.tx + a.r4 * b.ty + a.r5 * b.tz + a.ty;
    c.tz = a.r6 * b.tx + a.r7 * b.ty + a.r8 * b.tz + a.tz;
    return c;
}

}  // namespace

__global__ void __launch_bounds__(NT, 5) fk_kernel(
    const float* __restrict__ pos,   // [B,24,3]
    const float* __restrict__ rot,   // [B,24,4]
    float* __restrict__ out,         // [B,24,3]
    int B)
{
    // Per-pass buffers (pass = 12-joint half of the tree).
    // A: scalar rows, stride 129 ≡ 1 (mod 32): both staging scatter and
    //    per-thread column access conflict-free.
    // Q4: float4-native, 10 rows (leaf quats never staged); compute does one
    //    LDS.128 per joint (lanes hit consecutive 16B -> conflict-free).
    __shared__ float  A[36][NT + 1];
    __shared__ float4 Q4[10][NT + 1];

    const int tid = threadIdx.x;
    const int blockBase = blockIdx.x * NT;
    const int nb = min(NT, B - blockBase);
    const int nfp = nb * 9;    // pos float4s per pass
    const int nfq = nb * 12;   // quat float4s per pass (before leaf skip)

    const float4* gp4 = (const float4*)(pos + (size_t)blockBase * 72);
    const float4* gq4 = (const float4*)(rot + (size_t)blockBase * 96);
    float4* go4 = (float4*)(out + (size_t)blockBase * 72);

    auto stage = [&](int pass) {
#pragma unroll
        for (int i = 0; i < 9; ++i) {            // positions half (36 floats)
            int f = i * NT + tid;
            if (f < nfp) {
                int b = f / 9, k = f - b * 9;
                float4 v = __ldg(&gp4[b * 18 + pass * 9 + k]);
                A[4 * k + 0][b] = v.x;
                A[4 * k + 1][b] = v.y;
                A[4 * k + 2][b] = v.z;
                A[4 * k + 3][b] = v.w;
            }
        }
#pragma unroll
        for (int i = 0; i < 12; ++i) {           // quats half, leaf joints skipped
            int f = i * NT + tid;
            if (f < nfq) {
                int b = f / 12, jj = f - b * 12;
                // leaves: pass0 jj 10,11 (j10,j11); pass1 jj 3,10,11 (j15,j22,j23)
                bool need = (pass == 0) ? (jj < 10) : (jj < 10 && jj != 3);
                if (need) {
                    int row = (pass == 0 || jj < 3) ? jj : jj - 1;  // dense rows
                    Q4[row][b] = __ldg(&gq4[b * 24 + pass * 12 + jj]);
                }
            }
        }
    };
    auto flush = [&](int pass) {
#pragma unroll
        for (int i = 0; i < 9; ++i) {
            int f = i * NT + tid;
            if (f < nfp) {
                int b = f / 9, k = f - b * 9;
                float4 v;
                v.x = A[4 * k + 0][b];
                v.y = A[4 * k + 1][b];
                v.z = A[4 * k + 2][b];
                v.w = A[4 * k + 3][b];
                go4[b * 18 + pass * 9 + k] = v;
            }
        }
    };

    // jj = joint index within the pass's 12-joint window; row = Q4 row.
    auto local = [&](int row, int jj) -> X {
        float4 q = Q4[row][tid];   // single LDS.128
        return make_local(q, A[3 * jj + 0][tid], A[3 * jj + 1][tid],
                          A[3 * jj + 2][tid]);
    };
    auto putx = [&](int jj, const X& g) {   // output aliases consumed pos rows
        A[3 * jj + 0][tid] = g.tx;
        A[3 * jj + 1][tid] = g.ty;
        A[3 * jj + 2][tid] = g.tz;
    };
    auto putleaf = [&](int jj, const X& a) {  // leaf: translation only, no quat
        float px = A[3 * jj + 0][tid], py = A[3 * jj + 1][tid],
              pz = A[3 * jj + 2][tid];
        A[3 * jj + 0][tid] = a.r0 * px + a.r1 * py + a.r2 * pz + a.tx;
        A[3 * jj + 1][tid] = a.r3 * px + a.r4 * py + a.r5 * pz + a.ty;
        A[3 * jj + 2][tid] = a.r6 * px + a.r7 * py + a.r8 * pz + a.tz;
    };

    X g9;  // persists across passes in registers

    // ================= Pass 1: joints 0..11 (row == jj) =================
    stage(0);
    __syncthreads();
    if (tid < nb) {
        X g0 = local(0, 0);
        putx(0, g0);
        {
            X a = xmul(g0, local(1, 1)); putx(1, a);
            a = xmul(a, local(4, 4));    putx(4, a);
            a = xmul(a, local(7, 7));    putx(7, a);
            putleaf(10, a);
        }
        {
            X a = xmul(g0, local(2, 2)); putx(2, a);
            a = xmul(a, local(5, 5));    putx(5, a);
            a = xmul(a, local(8, 8));    putx(8, a);
            putleaf(11, a);
        }
        {
            X a = xmul(g0, local(3, 3)); putx(3, a);
            a = xmul(a, local(6, 6));    putx(6, a);
            g9 = xmul(a, local(9, 9));   putx(9, g9);
        }
    }
    __syncthreads();
    flush(0);
    __syncthreads();

    // ===== Pass 2: joints 12..23 (jj = j-12; row = jj<3 ? jj : jj-1) =====
    stage(1);
    __syncthreads();
    if (tid < nb) {
        {
            X a = xmul(g9, local(0, 0));  putx(0, a);   // j12
            putleaf(3, a);                               // j15
        }
        {
            X a = xmul(g9, local(1, 1));  putx(1, a);   // j13
            a = xmul(a, local(3, 4));     putx(4, a);   // j16
            a = xmul(a, local(5, 6));     putx(6, a);   // j18
            a = xmul(a, local(7, 8));     putx(8, a);   // j20
            putleaf(10, a);                              // j22
        }
        {
            X a = xmul(g9, local(2, 2));  putx(2, a);   // j14
            a = xmul(a, local(4, 5));     putx(5, a);   // j17
            a = xmul(a, local(6, 7));     putx(7, a);   // j19
            a = xmul(a, local(8, 9));     putx(9, a);   // j21
            putleaf(11, a);                              // j23
        }
    }
    __syncthreads();
    flush(1);
}

extern "C" void kernel_launch(void* const* d_in, const int* in_sizes, int n_in,
                              void* d_out, int out_size) {
    // metadata order: parents (int64, unused — tree is compile-time),
    //                 positions (B*24*3 f32), rotations (B*24*4 f32)
    const float* pos = (const float*)d_in[1];
    const float* rot = (const float*)d_in[2];
    float* out = (float*)d_out;

    int B = in_sizes[1] / 72;
    int grid = (B + NT - 1) / NT;
    fk_kernel<<<grid, NT>>>(pos, rot, out, B);
}

// round 9
// speedup vs baseline: 1.4065x; 1.4065x over previous
#include <cuda_runtime.h>

namespace {

constexpr int NT = 128;  // batches per block

struct X {
    float r0, r1, r2, r3, r4, r5, r6, r7, r8;  // 3x3 rotation, row-major
    float tx, ty, tz;                           // translation
};

// Local transform from (unnormalized) quat (w,x,y,z) + position.
// s = 2/|q|^2 — identical to normalize-then-rotmat.
__device__ __forceinline__ X make_local(float qw, float qx, float qy, float qz,
                                        float px, float py, float pz) {
    X o;
    float n = qw * qw + qx * qx + qy * qy + qz * qz;
    float s = __fdividef(2.0f, n);
    float x2 = qx * s, y2 = qy * s, z2 = qz * s;
    float xx = qx * x2, yy = qy * y2, zz = qz * z2;
    float xy = qx * y2, yz = qy * z2, xz = qx * z2;
    float wx = qw * x2, wy = qw * y2, wz = qw * z2;
    o.r0 = 1.0f - (yy + zz); o.r1 = xy - wz;          o.r2 = xz + wy;
    o.r3 = xy + wz;          o.r4 = 1.0f - (xx + zz); o.r5 = yz - wx;
    o.r6 = xz - wy;          o.r7 = yz + wx;          o.r8 = 1.0f - (xx + yy);
    o.tx = px; o.ty = py; o.tz = pz;
    return o;
}

// Affine compose: c = a ∘ b (a = parent global, b = child local)
__device__ __forceinline__ X xmul(const X& a, const X& b) {
    X c;
    c.r0 = a.r0 * b.r0 + a.r1 * b.r3 + a.r2 * b.r6;
    c.r1 = a.r0 * b.r1 + a.r1 * b.r4 + a.r2 * b.r7;
    c.r2 = a.r0 * b.r2 + a.r1 * b.r5 + a.r2 * b.r8;
    c.r3 = a.r3 * b.r0 + a.r4 * b.r3 + a.r5 * b.r6;
    c.r4 = a.r3 * b.r1 + a.r4 * b.r4 + a.r5 * b.r7;
    c.r5 = a.r3 * b.r2 + a.r4 * b.r5 + a.r5 * b.r8;
    c.r6 = a.r6 * b.r0 + a.r7 * b.r3 + a.r8 * b.r6;
    c.r7 = a.r6 * b.r1 + a.r7 * b.r4 + a.r8 * b.r7;
    c.r8 = a.r6 * b.r2 + a.r7 * b.r5 + a.r8 * b.r8;
    c.tx = a.r0 * b.tx + a.r1 * b.ty + a.r2 * b.tz + a.tx;
    c.ty = a.r3 * b.tx + a.r4 * b.ty + a.r5 * b.tz + a.ty;
    c.tz = a.r6 * b.tx + a.r7 * b.ty + a.r8 * b.tz + a.tz;
    return c;
}

}  // namespace

template <bool FULL>
__global__ void __launch_bounds__(NT, 5) fk_kernel(
    const float* __restrict__ pos,   // [B,24,3]
    const float* __restrict__ rot,   // [B,24,4]
    float* __restrict__ out,         // [B,24,3]
    int B)
{
    // Per-pass buffers (pass = 12-joint half of the tree). Identical layout to
    // the 45.2us kernel: scalar rows, stride 129 ≡ 1 (mod 32) -> conflict-free
    // for both staging scatter and per-thread column access.
    __shared__ float A[36][NT + 1];  // pos-in, then outputs, for current pass
    __shared__ float Q[48][NT + 1];  // quats for current pass (sparse leaf rows)

    const int tid = threadIdx.x;
    const int blockBase = blockIdx.x * NT;
    const int nb = FULL ? NT : min(NT, B - blockBase);
    const int nfp = nb * 9;    // pos float4s per pass
    const int nfq = nb * 12;   // quat float4s per pass

    const float4* gp4 = (const float4*)(pos + (size_t)blockBase * 72);
    const float4* gq4 = (const float4*)(rot + (size_t)blockBase * 96);
    float4* go4 = (float4*)(out + (size_t)blockBase * 72);

    auto stage = [&](int pass) {
#pragma unroll
        for (int i = 0; i < 9; ++i) {            // positions half
            int f = i * NT + tid;
            if (FULL || f < nfp) {
                int b = f / 9, k = f - b * 9;
                float4 v = __ldg(&gp4[b * 18 + pass * 9 + k]);
                A[4 * k + 0][b] = v.x;
                A[4 * k + 1][b] = v.y;
                A[4 * k + 2][b] = v.z;
                A[4 * k + 3][b] = v.w;
            }
        }
#pragma unroll
        for (int i = 0; i < 12; ++i) {           // quats half, leaf joints skipped
            int f = i * NT + tid;
            if (FULL || f < nfq) {
                int b = f / 12, jj = f - b * 12;
                // leaves: pass0 jj 10,11 (j10,j11); pass1 jj 3,10,11 (j15,j22,j23)
                bool need = (pass == 0) ? (jj < 10) : (jj < 10 && jj != 3);
                if (need) {
                    float4 v = __ldg(&gq4[b * 24 + pass * 12 + jj]);
                    Q[4 * jj + 0][b] = v.x;
                    Q[4 * jj + 1][b] = v.y;
                    Q[4 * jj + 2][b] = v.z;
                    Q[4 * jj + 3][b] = v.w;
                }
            }
        }
    };
    auto flush = [&](int pass) {
#pragma unroll
        for (int i = 0; i < 9; ++i) {
            int f = i * NT + tid;
            if (FULL || f < nfp) {
                int b = f / 9, k = f - b * 9;
                float4 v;
                v.x = A[4 * k + 0][b];
                v.y = A[4 * k + 1][b];
                v.z = A[4 * k + 2][b];
                v.w = A[4 * k + 3][b];
                go4[b * 18 + pass * 9 + k] = v;
            }
        }
    };

    // jj = joint index within the pass's 12-joint window.
    auto local = [&](int jj) -> X {
        return make_local(Q[4 * jj + 0][tid], Q[4 * jj + 1][tid],
                          Q[4 * jj + 2][tid], Q[4 * jj + 3][tid],
                          A[3 * jj + 0][tid], A[3 * jj + 1][tid],
                          A[3 * jj + 2][tid]);
    };
    auto putx = [&](int jj, const X& g) {   // output aliases consumed pos rows
        A[3 * jj + 0][tid] = g.tx;
        A[3 * jj + 1][tid] = g.ty;
        A[3 * jj + 2][tid] = g.tz;
    };
    auto putleaf = [&](int jj, const X& a) {  // leaf: translation only, no quat
        float px = A[3 * jj + 0][tid], py = A[3 * jj + 1][tid],
              pz = A[3 * jj + 2][tid];
        A[3 * jj + 0][tid] = a.r0 * px + a.r1 * py + a.r2 * pz + a.tx;
        A[3 * jj + 1][tid] = a.r3 * px + a.r4 * py + a.r5 * pz + a.ty;
        A[3 * jj + 2][tid] = a.r6 * px + a.r7 * py + a.r8 * pz + a.tz;
    };

    X g9;  // persists across passes in registers

    // ================= Pass 1: joints 0..11 =================
    stage(0);
    __syncthreads();
    if (FULL || tid < nb) {
        X g0 = local(0);
        putx(0, g0);
        {
            X a = xmul(g0, local(1)); putx(1, a);
            a = xmul(a, local(4));    putx(4, a);
            a = xmul(a, local(7));    putx(7, a);
            putleaf(10, a);
        }
        {
            X a = xmul(g0, local(2)); putx(2, a);
            a = xmul(a, local(5));    putx(5, a);
            a = xmul(a, local(8));    putx(8, a);
            putleaf(11, a);
        }
        {
            X a = xmul(g0, local(3)); putx(3, a);
            a = xmul(a, local(6));    putx(6, a);
            g9 = xmul(a, local(9));   putx(9, g9);
        }
    }
    __syncthreads();
    flush(0);
    __syncthreads();

    // ================= Pass 2: joints 12..23 (jj = j-12) =================
    stage(1);
    __syncthreads();
    if (FULL || tid < nb) {
        {
            X a = xmul(g9, local(0));  putx(0, a);   // j12
            putleaf(3, a);                            // j15
        }
        {
            X a = xmul(g9, local(1));  putx(1, a);   // j13
            a = xmul(a, local(4));     putx(4, a);   // j16
            a = xmul(a, local(6));     putx(6, a);   // j18
            a = xmul(a, local(8));     putx(8, a);   // j20
            putleaf(10, a);                           // j22
        }
        {
            X a = xmul(g9, local(2));  putx(2, a);   // j14
            a = xmul(a, local(5));     putx(5, a);   // j17
            a = xmul(a, local(7));     putx(7, a);   // j19
            a = xmul(a, local(9));     putx(9, a);   // j21
            putleaf(11, a);                           // j23
        }
    }
    __syncthreads();
    flush(1);
}

extern "C" void kernel_launch(void* const* d_in, const int* in_sizes, int n_in,
                              void* d_out, int out_size) {
    // metadata order: parents (int64, unused — tree is compile-time),
    //                 positions (B*24*3 f32), rotations (B*24*4 f32)
    const float* pos = (const float*)d_in[1];
    const float* rot = (const float*)d_in[2];
    float* out = (float*)d_out;

    int B = in_sizes[1] / 72;
    int grid = (B + NT - 1) / NT;
    if (B % NT == 0)
        fk_kernel<true><<<grid, NT>>>(pos, rot, out, B);
    else
        fk_kernel<false><<<grid, NT>>>(pos, rot, out, B);
}

// round 10
// speedup vs baseline: 1.4843x; 1.0553x over previous
#include <cuda_runtime.h>

namespace {

constexpr int NT = 128;  // batches per block

// Global transform as (quaternion, translation, scale): rotation = R(P/|P|),
// s = 2/|P|^2 cached for rotate-by-P. 8 floats vs 12 for a 3x4 matrix.
struct G {
    float qw, qx, qy, qz;
    float tx, ty, tz;
    float s;
};

// p' = R(P/|P|) * p + t   using  v' = v + s*( w*(qv x v) + qv x (qv x v) ).
// Exactly equals the reference's normalize->rotmat->matvec.
__device__ __forceinline__ void rot_point(const G& g, float px, float py, float pz,
                                          float& ox, float& oy, float& oz) {
    float t1x = g.qy * pz - g.qz * py;
    float t1y = g.qz * px - g.qx * pz;
    float t1z = g.qx * py - g.qy * px;
    float c2x = g.qy * t1z - g.qz * t1y;
    float c2y = g.qz * t1x - g.qx * t1z;
    float c2z = g.qx * t1y - g.qy * t1x;
    ox = fmaf(g.s, fmaf(g.qw, t1x, c2x), g.tx + px);
    oy = fmaf(g.s, fmaf(g.qw, t1y, c2y), g.ty + py);
    oz = fmaf(g.s, fmaf(g.qw, t1z, c2z), g.tz + pz);
}

// Child global = parent ∘ local(q_l raw, p_l). Hamilton product composes the
// rotations (|a⊗b| = |a||b| keeps the unnormalized form consistent).
__device__ __forceinline__ G compose(const G& a, float lw, float lx, float ly,
                                     float lz, float px, float py, float pz) {
    G c;
    rot_point(a, px, py, pz, c.tx, c.ty, c.tz);
    c.qw = a.qw * lw - a.qx * lx - a.qy * ly - a.qz * lz;
    c.qx = a.qw * lx + a.qx * lw + a.qy * lz - a.qz * ly;
    c.qy = a.qw * ly - a.qx * lz + a.qy * lw + a.qz * lx;
    c.qz = a.qw * lz + a.qx * ly - a.qy * lx + a.qz * lw;
    float n = c.qw * c.qw + c.qx * c.qx + c.qy * c.qy + c.qz * c.qz;
    c.s = __fdividef(2.0f, n);
    return c;
}

}  // namespace

template <bool FULL>
__global__ void __launch_bounds__(NT, 5) fk_kernel(
    const float* __restrict__ pos,   // [B,24,3]
    const float* __restrict__ rot,   // [B,24,4]
    float* __restrict__ out,         // [B,24,3]
    int B)
{
    // Staging identical to the 39.7us kernel: per-pass (12-joint) buffers,
    // scalar rows, stride 129 ≡ 1 (mod 32) -> conflict-free both phases.
    __shared__ float A[36][NT + 1];  // pos-in, then outputs, for current pass
    __shared__ float Q[48][NT + 1];  // quats for current pass (sparse leaf rows)

    const int tid = threadIdx.x;
    const int blockBase = blockIdx.x * NT;
    const int nb = FULL ? NT : min(NT, B - blockBase);
    const int nfp = nb * 9;    // pos float4s per pass
    const int nfq = nb * 12;   // quat float4s per pass

    const float4* gp4 = (const float4*)(pos + (size_t)blockBase * 72);
    const float4* gq4 = (const float4*)(rot + (size_t)blockBase * 96);
    float4* go4 = (float4*)(out + (size_t)blockBase * 72);

    auto stage = [&](int pass) {
#pragma unroll
        for (int i = 0; i < 9; ++i) {            // positions half
            int f = i * NT + tid;
            if (FULL || f < nfp) {
                int b = f / 9, k = f - b * 9;
                float4 v = __ldg(&gp4[b * 18 + pass * 9 + k]);
                A[4 * k + 0][b] = v.x;
                A[4 * k + 1][b] = v.y;
                A[4 * k + 2][b] = v.z;
                A[4 * k + 3][b] = v.w;
            }
        }
#pragma unroll
        for (int i = 0; i < 12; ++i) {           // quats half, leaf joints skipped
            int f = i * NT + tid;
            if (FULL || f < nfq) {
                int b = f / 12, jj = f - b * 12;
                // leaves: pass0 jj 10,11 (j10,j11); pass1 jj 3,10,11 (j15,j22,j23)
                bool need = (pass == 0) ? (jj < 10) : (jj < 10 && jj != 3);
                if (need) {
                    float4 v = __ldg(&gq4[b * 24 + pass * 12 + jj]);
                    Q[4 * jj + 0][b] = v.x;
                    Q[4 * jj + 1][b] = v.y;
                    Q[4 * jj + 2][b] = v.z;
                    Q[4 * jj + 3][b] = v.w;
                }
            }
        }
    };
    auto flush = [&](int pass) {
#pragma unroll
        for (int i = 0; i < 9; ++i) {
            int f = i * NT + tid;
            if (FULL || f < nfp) {
                int b = f / 9, k = f - b * 9;
                float4 v;
                v.x = A[4 * k + 0][b];
                v.y = A[4 * k + 1][b];
                v.z = A[4 * k + 2][b];
                v.w = A[4 * k + 3][b];
                go4[b * 18 + pass * 9 + k] = v;
            }
        }
    };

    // jj = joint index within the pass's 12-joint window.
    auto child = [&](const G& par, int jj) -> G {
        return compose(par, Q[4 * jj + 0][tid], Q[4 * jj + 1][tid],
                       Q[4 * jj + 2][tid], Q[4 * jj + 3][tid],
                       A[3 * jj + 0][tid], A[3 * jj + 1][tid],
                       A[3 * jj + 2][tid]);
    };
    auto putx = [&](int jj, const G& g) {   // output aliases consumed pos rows
        A[3 * jj + 0][tid] = g.tx;
        A[3 * jj + 1][tid] = g.ty;
        A[3 * jj + 2][tid] = g.tz;
    };
    auto putleaf = [&](int jj, const G& a) {  // leaf: translation only, no quat
        float ox, oy, oz;
        rot_point(a, A[3 * jj + 0][tid], A[3 * jj + 1][tid], A[3 * jj + 2][tid],
                  ox, oy, oz);
        A[3 * jj + 0][tid] = ox;
        A[3 * jj + 1][tid] = oy;
        A[3 * jj + 2][tid] = oz;
    };

    G g9;  // persists across passes in registers

    // ================= Pass 1: joints 0..11 =================
    stage(0);
    __syncthreads();
    if (FULL || tid < nb) {
        G g0;
        g0.qw = Q[0][tid]; g0.qx = Q[1][tid];
        g0.qy = Q[2][tid]; g0.qz = Q[3][tid];
        float n0 = g0.qw * g0.qw + g0.qx * g0.qx + g0.qy * g0.qy + g0.qz * g0.qz;
        g0.s = __fdividef(2.0f, n0);
        g0.tx = A[0][tid]; g0.ty = A[1][tid]; g0.tz = A[2][tid];
        // joint-0 output == p0, already resident in A rows 0..2: no store needed.
        {
            G a = child(g0, 1); putx(1, a);
            a = child(a, 4);    putx(4, a);
            a = child(a, 7);    putx(7, a);
            putleaf(10, a);
        }
        {
            G a = child(g0, 2); putx(2, a);
            a = child(a, 5);    putx(5, a);
            a = child(a, 8);    putx(8, a);
            putleaf(11, a);
        }
        {
            G a = child(g0, 3); putx(3, a);
            a = child(a, 6);    putx(6, a);
            g9 = child(a, 9);   putx(9, g9);
        }
    }
    __syncthreads();
    flush(0);
    __syncthreads();

    // ================= Pass 2: joints 12..23 (jj = j-12) =================
    stage(1);
    __syncthreads();
    if (FULL || tid < nb) {
        {
            G a = child(g9, 0);  putx(0, a);   // j12
            putleaf(3, a);                      // j15
        }
        {
            G a = child(g9, 1);  putx(1, a);   // j13
            a = child(a, 4);     putx(4, a);   // j16
            a = child(a, 6);     putx(6, a);   // j18
            a = child(a, 8);     putx(8, a);   // j20
            putleaf(10, a);                     // j22
        }
        {
            G a = child(g9, 2);  putx(2, a);   // j14
            a = child(a, 5);     putx(5, a);   // j17
            a = child(a, 7);     putx(7, a);   // j19
            a = child(a, 9);     putx(9, a);   // j21
            putleaf(11, a);                     // j23
        }
    }
    __syncthreads();
    flush(1);
}

extern "C" void kernel_launch(void* const* d_in, const int* in_sizes, int n_in,
                              void* d_out, int out_size) {
    // metadata order: parents (int64, unused — tree is compile-time),
    //                 positions (B*24*3 f32), rotations (B*24*4 f32)
    const float* pos = (const float*)d_in[1];
    const float* rot = (const float*)d_in[2];
    float* out = (float*)d_out;

    int B = in_sizes[1] / 72;
    int grid = (B + NT - 1) / NT;
    if (B % NT == 0)
        fk_kernel<true><<<grid, NT>>>(pos, rot, out, B);
    else
        fk_kernel<false><<<grid, NT>>>(pos, rot, out, B);
}

// round 11
// speedup vs baseline: 1.7250x; 1.1622x over previous
#include <cuda_runtime.h>

namespace {

constexpr int NT = 128;   // threads per block
constexpr int NB = 32;    // batches per block (4 threads per batch)

// Global transform as (quaternion, translation, scale): rotation = R(P/|P|),
// s = 2/|P|^2. Hamilton-product composition keeps unnormalized form exact.
struct G {
    float qw, qx, qy, qz;
    float tx, ty, tz;
    float s;
};

// p' = R(P/|P|)*p + t  via  v' = v + s*( w*(qv x v) + qv x (qv x v) ).
__device__ __forceinline__ void rot_point(const G& g, float px, float py, float pz,
                                          float& ox, float& oy, float& oz) {
    float t1x = g.qy * pz - g.qz * py;
    float t1y = g.qz * px - g.qx * pz;
    float t1z = g.qx * py - g.qy * px;
    float c2x = g.qy * t1z - g.qz * t1y;
    float c2y = g.qz * t1x - g.qx * t1z;
    float c2z = g.qx * t1y - g.qy * t1x;
    ox = fmaf(g.s, fmaf(g.qw, t1x, c2x), g.tx + px);
    oy = fmaf(g.s, fmaf(g.qw, t1y, c2y), g.ty + py);
    oz = fmaf(g.s, fmaf(g.qw, t1z, c2z), g.tz + pz);
}

__device__ __forceinline__ G compose(const G& a, float lw, float lx, float ly,
                                     float lz, float px, float py, float pz) {
    G c;
    rot_point(a, px, py, pz, c.tx, c.ty, c.tz);
    c.qw = a.qw * lw - a.qx * lx - a.qy * ly - a.qz * lz;
    c.qx = a.qw * lx + a.qx * lw + a.qy * lz - a.qz * ly;
    c.qy = a.qw * ly - a.qx * lz + a.qy * lw + a.qz * lx;
    c.qz = a.qw * lz + a.qx * ly - a.qy * lx + a.qz * lw;
    float n = c.qw * c.qw + c.qx * c.qx + c.qy * c.qy + c.qz * c.qz;
    c.s = __fdividef(2.0f, n);
    return c;
}

__device__ __forceinline__ float shfl_from(float v, int srcLane) {
    return __shfl_sync(0xffffffffu, v, srcLane, 32);
}

}  // namespace

template <bool FULL>
__global__ void __launch_bounds__(NT, 8) fk_kernel(
    const float* __restrict__ pos,   // [B,24,3]
    const float* __restrict__ rot,   // [B,24,4]
    float* __restrict__ out,         // [B,24,3]
    int B)
{
    // Single-pass buffers for NB=32 batches. Row stride 33 ≡ 1 (mod 32).
    // A: positions in, outputs aliased over consumed rows. Q: quats (leaf rows unused).
    __shared__ float A[72][NB + 1];
    __shared__ float Q[88][NB + 1];

    const int tid = threadIdx.x;
    const int lane = tid & 31;
    const int sub = tid & 3;          // role within the batch quad
    const int col = tid >> 2;         // batch column 0..31
    const int blockBase = blockIdx.x * NB;
    const int nb = FULL ? NB : min(NB, B - blockBase);
    const int nfp = FULL ? NB * 18 : nb * 18;   // pos float4 count
    const int nfq = FULL ? NB * 24 : nb * 24;   // quat float4 slots

    const float4* gp4 = (const float4*)(pos + (size_t)blockBase * 72);
    const float4* gq4 = (const float4*)(rot + (size_t)blockBase * 96);
    float4* go4 = (float4*)(out + (size_t)blockBase * 72);

    // ---- Stage: coalesced global -> smem transpose ----
#pragma unroll
    for (int i = 0; i < 5; ++i) {               // positions: 18 f4/batch
        int f = i * NT + tid;
        if (f < nfp) {
            int b = f / 18, k = f - b * 18;
            float4 v = __ldg(&gp4[f]);
            A[4 * k + 0][b] = v.x;
            A[4 * k + 1][b] = v.y;
            A[4 * k + 2][b] = v.z;
            A[4 * k + 3][b] = v.w;
        }
    }
#pragma unroll
    for (int i = 0; i < 6; ++i) {               // quats: 24 f4/batch, skip leaves
        int f = i * NT + tid;
        if (f < nfq) {
            int b = f / 24, j = f - b * 24;
            // leaves 10,11,15,22,23 never needed
            if (j != 10 && j != 11 && j != 15 && j < 22) {
                float4 v = __ldg(&gq4[f]);
                Q[4 * j + 0][b] = v.x;
                Q[4 * j + 1][b] = v.y;
                Q[4 * j + 2][b] = v.z;
                Q[4 * j + 3][b] = v.w;
            }
        }
    }
    __syncthreads();

    // ---- Compute: 4 lanes per batch walk parallel chains in lockstep ----
    const bool ok = FULL || (col < nb);

    auto localcompose = [&](const G& a, int j) -> G {
        return compose(a, Q[4 * j + 0][col], Q[4 * j + 1][col],
                       Q[4 * j + 2][col], Q[4 * j + 3][col],
                       A[3 * j + 0][col], A[3 * j + 1][col], A[3 * j + 2][col]);
    };
    auto putx = [&](int j, const G& g) {
        A[3 * j + 0][col] = g.tx;
        A[3 * j + 1][col] = g.ty;
        A[3 * j + 2][col] = g.tz;
    };
    auto putleaf = [&](int j, const G& a) {
        float ox, oy, oz;
        rot_point(a, A[3 * j + 0][col], A[3 * j + 1][col], A[3 * j + 2][col],
                  ox, oy, oz);
        A[3 * j + 0][col] = ox;
        A[3 * j + 1][col] = oy;
        A[3 * j + 2][col] = oz;
    };

    // Root (all lanes; smem reads broadcast within the quad).
    G g;
    g.qw = Q[0][col]; g.qx = Q[1][col]; g.qy = Q[2][col]; g.qz = Q[3][col];
    {
        float n0 = g.qw * g.qw + g.qx * g.qx + g.qy * g.qy + g.qz * g.qz;
        g.s = __fdividef(2.0f, n0);
    }
    g.tx = A[0][col]; g.ty = A[1][col]; g.tz = A[2][col];
    // out joint 0 == pos 0, already resident in A rows 0..2.

    // Phase 1: chains {1,4,7} / {2,5,8} / {3,6,9} (sub3 duplicates sub2).
    const int s2 = (sub < 2) ? sub : 2;
#pragma unroll
    for (int k = 0; k < 3; ++k) {
        int j = 3 * k + 1 + s2;
        g = localcompose(g, j);
        if (ok && sub != 3) putx(j, g);
    }
    if (ok && sub < 2) putleaf(10 + sub, g);     // leaves 10, 11

    // Broadcast g9 from the quad's sub2 lane.
    {
        int src = (lane & ~3) | 2;
        G h;
        h.qw = shfl_from(g.qw, src); h.qx = shfl_from(g.qx, src);
        h.qy = shfl_from(g.qy, src); h.qz = shfl_from(g.qz, src);
        h.tx = shfl_from(g.tx, src); h.ty = shfl_from(g.ty, src);
        h.tz = shfl_from(g.tz, src); h.s  = shfl_from(g.s,  src);
        g = h;
    }

    // Phase 2: sub0: 12 -> leaf15; sub1: 13,16,18,20 -> leaf22;
    //          sub2: 14,17,19,21 -> leaf23; sub3 idle.
    if (sub < 3) {
        int j = 12 + sub;
        g = localcompose(g, j);
        if (ok) putx(j, g);
    }
#pragma unroll
    for (int k = 1; k < 4; ++k) {
        if (sub == 1 || sub == 2) {
            int j = 13 + 2 * k + sub;            // 16/17, 18/19, 20/21
            g = localcompose(g, j);
            if (ok) putx(j, g);
        }
    }
    {
        int lj = (sub == 0) ? 15 : (sub == 1) ? 22 : (sub == 2) ? 23 : -1;
        if (ok && lj >= 0) putleaf(lj, g);
    }

    __syncthreads();

    // ---- Flush: coalesced smem -> global ----
#pragma unroll
    for (int i = 0; i < 5; ++i) {
        int f = i * NT + tid;
        if (f < nfp) {
            int b = f / 18, k = f - b * 18;
            float4 v;
            v.x = A[4 * k + 0][b];
            v.y = A[4 * k + 1][b];
            v.z = A[4 * k + 2][b];
            v.w = A[4 * k + 3][b];
            go4[f] = v;
        }
    }
}

extern "C" void kernel_launch(void* const* d_in, const int* in_sizes, int n_in,
                              void* d_out, int out_size) {
    // metadata order: parents (int64, unused — tree is compile-time),
    //                 positions (B*24*3 f32), rotations (B*24*4 f32)
    const float* pos = (const float*)d_in[1];
    const float* rot = (const float*)d_in[2];
    float* out = (float*)d_out;

    int B = in_sizes[1] / 72;
    int grid = (B + NB - 1) / NB;
    if (B % NB == 0)
        fk_kernel<true><<<grid, NT>>>(pos, rot, out, B);
    else
        fk_kernel<false><<<grid, NT>>>(pos, rot, out, B);
}

// round 12
// speedup vs baseline: 2.0374x; 1.1811x over previous
#include <cuda_runtime.h>

namespace {

constexpr int NT = 128;   // threads per block
constexpr int NB = 32;    // batches per block (4 threads per batch)

constexpr int AS = 76;    // A stride (floats/batch): 76*4B ≡ 0 mod 16, 76 ≡ 12 mod 32
constexpr int QS = 92;    // Q stride: 92*4B ≡ 0 mod 16, 92 ≡ 28 mod 32

// Global transform as (quaternion, translation, scale): rotation = R(P/|P|),
// s = 2/|P|^2. Hamilton-product composition keeps unnormalized form exact.
struct G {
    float qw, qx, qy, qz;
    float tx, ty, tz;
    float s;
};

// p' = R(P/|P|)*p + t  via  v' = v + s*( w*(qv x v) + qv x (qv x v) ).
__device__ __forceinline__ void rot_point(const G& g, float px, float py, float pz,
                                          float& ox, float& oy, float& oz) {
    float t1x = g.qy * pz - g.qz * py;
    float t1y = g.qz * px - g.qx * pz;
    float t1z = g.qx * py - g.qy * px;
    float c2x = g.qy * t1z - g.qz * t1y;
    float c2y = g.qz * t1x - g.qx * t1z;
    float c2z = g.qx * t1y - g.qy * t1x;
    ox = fmaf(g.s, fmaf(g.qw, t1x, c2x), g.tx + px);
    oy = fmaf(g.s, fmaf(g.qw, t1y, c2y), g.ty + py);
    oz = fmaf(g.s, fmaf(g.qw, t1z, c2z), g.tz + pz);
}

__device__ __forceinline__ G compose(const G& a, float4 q, float px, float py,
                                     float pz) {
    // q = (w,x,y,z) raw local quat
    G c;
    rot_point(a, px, py, pz, c.tx, c.ty, c.tz);
    c.qw = a.qw * q.x - a.qx * q.y - a.qy * q.z - a.qz * q.w;
    c.qx = a.qw * q.y + a.qx * q.x + a.qy * q.w - a.qz * q.z;
    c.qy = a.qw * q.z - a.qx * q.w + a.qy * q.x + a.qz * q.y;
    c.qz = a.qw * q.w + a.qx * q.z - a.qy * q.y + a.qz * q.x;
    float n = c.qw * c.qw + c.qx * c.qx + c.qy * c.qy + c.qz * c.qz;
    c.s = __fdividef(2.0f, n);
    return c;
}

__device__ __forceinline__ float shfl_from(float v, int srcLane) {
    return __shfl_sync(0xffffffffu, v, srcLane, 32);
}

}  // namespace

template <bool FULL>
__global__ void __launch_bounds__(NT, 8) fk_kernel(
    const float* __restrict__ pos,   // [B,24,3]
    const float* __restrict__ rot,   // [B,24,4]
    float* __restrict__ out,         // [B,24,3]
    int B)
{
    // Batch-major smem: vectorized staging (STS.128/LDS.128) and bank-rotated
    // per-quad access (stride 12 / 28 mod 32 across the warp's 8 quads).
    __shared__ float4 A4[NB * (AS / 4)];   // 32*19 f4 = 9.5KB: pos in, outputs over
    __shared__ float4 Q4[NB * (QS / 4)];   // 32*23 f4 = 11.5KB: quats (leaf slots unused)
    float* A = (float*)A4;
    float* Q = (float*)Q4;

    const int tid = threadIdx.x;
    const int lane = tid & 31;
    const int sub = tid & 3;          // role within the batch quad
    const int col = tid >> 2;         // batch 0..31 within block
    const int blockBase = blockIdx.x * NB;
    const int nb = FULL ? NB : min(NB, B - blockBase);
    const int nfp = nb * 18;          // pos float4 count
    const int nfq = nb * 24;          // quat float4 slots

    const float4* gp4 = (const float4*)(pos + (size_t)blockBase * 72);
    const float4* gq4 = (const float4*)(rot + (size_t)blockBase * 96);
    float4* go4 = (float4*)(out + (size_t)blockBase * 72);

    // ---- Stage: coalesced global -> batch-major smem (vector stores) ----
#pragma unroll
    for (int i = 0; i < 5; ++i) {               // positions: 18 f4/batch
        int f = i * NT + tid;
        if (f < nfp) {
            int b = f / 18, k = f - b * 18;
            A4[b * (AS / 4) + k] = __ldg(&gp4[f]);
        }
    }
#pragma unroll
    for (int i = 0; i < 6; ++i) {               // quats: 24 f4/batch, skip leaves
        int f = i * NT + tid;
        if (f < nfq) {
            int b = f / 24, j = f - b * 24;
            if (j != 10 && j != 11 && j != 15 && j < 22) {
                Q4[b * (QS / 4) + j] = __ldg(&gq4[f]);
            }
        }
    }
    __syncthreads();

    // ---- Compute: 4 lanes per batch, parallel chains in lockstep ----
    const bool ok = FULL || (col < nb);
    const float* Ab = A + col * AS;
    float* Aw = A + col * AS;
    const float4* Qb = Q4 + col * (QS / 4);

    auto localcompose = [&](const G& a, int j) -> G {
        float4 q = Qb[j];                        // one LDS.128, bank-rotated
        return compose(a, q, Ab[3 * j + 0], Ab[3 * j + 1], Ab[3 * j + 2]);
    };
    auto putx = [&](int j, const G& g) {
        Aw[3 * j + 0] = g.tx;
        Aw[3 * j + 1] = g.ty;
        Aw[3 * j + 2] = g.tz;
    };
    auto putleaf = [&](int j, const G& a) {
        float ox, oy, oz;
        rot_point(a, Ab[3 * j + 0], Ab[3 * j + 1], Ab[3 * j + 2], ox, oy, oz);
        Aw[3 * j + 0] = ox;
        Aw[3 * j + 1] = oy;
        Aw[3 * j + 2] = oz;
    };

    // Root (all lanes; quad lanes read identical addresses -> broadcast).
    G g;
    {
        float4 q0 = Qb[0];
        g.qw = q0.x; g.qx = q0.y; g.qy = q0.z; g.qz = q0.w;
        float n0 = g.qw * g.qw + g.qx * g.qx + g.qy * g.qy + g.qz * g.qz;
        g.s = __fdividef(2.0f, n0);
        g.tx = Ab[0]; g.ty = Ab[1]; g.tz = Ab[2];
    }
    // out joint 0 == pos 0: already resident in A words 0..2.

    // Phase 1: chains {1,4,7} / {2,5,8} / {3,6,9} (sub3 duplicates sub2).
    const int s2 = (sub < 2) ? sub : 2;
#pragma unroll
    for (int k = 0; k < 3; ++k) {
        int j = 3 * k + 1 + s2;
        g = localcompose(g, j);
        if (ok && sub != 3) putx(j, g);
    }
    if (ok && sub < 2) putleaf(10 + sub, g);     // leaves 10, 11

    // Broadcast g9 from the quad's sub2 lane.
    {
        int src = (lane & ~3) | 2;
        G h;
        h.qw = shfl_from(g.qw, src); h.qx = shfl_from(g.qx, src);
        h.qy = shfl_from(g.qy, src); h.qz = shfl_from(g.qz, src);
        h.tx = shfl_from(g.tx, src); h.ty = shfl_from(g.ty, src);
        h.tz = shfl_from(g.tz, src); h.s  = shfl_from(g.s,  src);
        g = h;
    }

    // Phase 2: sub0: 12 -> leaf15; sub1: 13,16,18,20 -> leaf22;
    //          sub2: 14,17,19,21 -> leaf23; sub3 idle.
    if (sub < 3) {
        int j = 12 + sub;
        g = localcompose(g, j);
        if (ok) putx(j, g);
    }
#pragma unroll
    for (int k = 1; k < 4; ++k) {
        if (sub == 1 || sub == 2) {
            int j = 13 + 2 * k + sub;            // 16/17, 18/19, 20/21
            g = localcompose(g, j);
            if (ok) putx(j, g);
        }
    }
    {
        int lj = (sub == 0) ? 15 : (sub == 1) ? 22 : (sub == 2) ? 23 : -1;
        if (ok && lj >= 0) putleaf(lj, g);
    }

    __syncthreads();

    // ---- Flush: batch-major smem -> coalesced global (vector loads) ----
#pragma unroll
    for (int i = 0; i < 5; ++i) {
        int f = i * NT + tid;
        if (f < nfp) {
            int b = f / 18, k = f - b * 18;
            go4[f] = A4[b * (AS / 4) + k];
        }
    }
}

extern "C" void kernel_launch(void* const* d_in, const int* in_sizes, int n_in,
                              void* d_out, int out_size) {
    // metadata order: parents (int64, unused — tree is compile-time),
    //                 positions (B*24*3 f32), rotations (B*24*4 f32)
    const float* pos = (const float*)d_in[1];
    const float* rot = (const float*)d_in[2];
    float* out = (float*)d_out;

    int B = in_sizes[1] / 72;
    int grid = (B + NB - 1) / NB;
    if (B % NB == 0)
        fk_kernel<true><<<grid, NT>>>(pos, rot, out, B);
    else
        fk_kernel<false><<<grid, NT>>>(pos, rot, out, B);
}

// round 16
// speedup vs baseline: 2.2273x; 1.0932x over previous
#include <cuda_runtime.h>
#include <cstdint>

namespace {

constexpr int NT = 128;   // threads per block
constexpr int NB = 32;    // batches per block (4 threads per batch)

constexpr int AS = 76;    // A stride (floats/batch): 76*4B ≡ 0 mod 16, 76 ≡ 12 mod 32
constexpr int QS = 92;    // Q stride: 92*4B ≡ 0 mod 16, 92 ≡ 28 mod 32

// Joints whose quaternions are needed (all but leaves 10,11,15,22,23).
constexpr unsigned QMASK =
    0xFFFFFFu ^ ((1u << 10) | (1u << 11) | (1u << 15) | (1u << 22) | (1u << 23));

// Global transform as (quaternion, translation, scale): rotation = R(P/|P|),
// s = 2/|P|^2. Hamilton-product composition keeps unnormalized form exact.
struct G {
    float qw, qx, qy, qz;
    float tx, ty, tz;
    float s;
};

// p' = R(P/|P|)*p + t  via  v' = v + s*( w*(qv x v) + qv x (qv x v) ).
__device__ __forceinline__ void rot_point(const G& g, float px, float py, float pz,
                                          float& ox, float& oy, float& oz) {
    float t1x = g.qy * pz - g.qz * py;
    float t1y = g.qz * px - g.qx * pz;
    float t1z = g.qx * py - g.qy * px;
    float c2x = g.qy * t1z - g.qz * t1y;
    float c2y = g.qz * t1x - g.qx * t1z;
    float c2z = g.qx * t1y - g.qy * t1x;
    ox = fmaf(g.s, fmaf(g.qw, t1x, c2x), g.tx + px);
    oy = fmaf(g.s, fmaf(g.qw, t1y, c2y), g.ty + py);
    oz = fmaf(g.s, fmaf(g.qw, t1z, c2z), g.tz + pz);
}

__device__ __forceinline__ G compose(const G& a, float4 q, float px, float py,
                                     float pz) {
    // q = (w,x,y,z) raw local quat
    G c;
    rot_point(a, px, py, pz, c.tx, c.ty, c.tz);
    c.qw = a.qw * q.x - a.qx * q.y - a.qy * q.z - a.qz * q.w;
    c.qx = a.qw * q.y + a.qx * q.x + a.qy * q.w - a.qz * q.z;
    c.qy = a.qw * q.z - a.qx * q.w + a.qy * q.x + a.qz * q.y;
    c.qz = a.qw * q.w + a.qx * q.z - a.qy * q.y + a.qz * q.x;
    float n = c.qw * c.qw + c.qx * c.qx + c.qy * c.qy + c.qz * c.qz;
    c.s = __fdividef(2.0f, n);
    return c;
}

__device__ __forceinline__ float shfl_from(float v, int srcLane) {
    return __shfl_sync(0xffffffffu, v, srcLane, 32);
}

// 16B global->shared async copy (no register landing zone).
__device__ __forceinline__ void cp16(unsigned int dst_smem, const void* src) {
    asm volatile("cp.async.cg.shared.global [%0], [%1], 16;\n"
                 :: "r"(dst_smem), "l"(src));
}

}  // namespace

template <bool FULL>
__global__ void __launch_bounds__(NT, 10) fk_kernel(
    const float* __restrict__ pos,   // [B,24,3]
    const float* __restrict__ rot,   // [B,24,4]
    float* __restrict__ out,         // [B,24,3]
    int B)
{
    // Batch-major smem: vectorized staging and bank-rotated per-quad access
    // (strides 12 / 28 mod 32 rotate across the warp's 8 quads).
    __shared__ float4 A4[NB * (AS / 4)];   // pos in, outputs aliased over
    __shared__ float4 Q4[NB * (QS / 4)];   // quats (leaf slots never written)
    float* A = (float*)A4;

    const int tid = threadIdx.x;
    const int lane = tid & 31;
    const int sub = tid & 3;          // role within the batch quad
    const int col = tid >> 2;         // batch 0..31 within block
    const int blockBase = blockIdx.x * NB;
    const int nb = FULL ? NB : min(NB, B - blockBase);
    const int nfp = nb * 18;          // pos float4 count
    const int nfq = nb * 24;          // quat float4 slots

    const float4* gp4 = (const float4*)(pos + (size_t)blockBase * 72);
    const float4* gq4 = (const float4*)(rot + (size_t)blockBase * 96);
    float4* go4 = (float4*)(out + (size_t)blockBase * 72);

    const unsigned int sA = (unsigned int)__cvta_generic_to_shared(A4);
    const unsigned int sQ = (unsigned int)__cvta_generic_to_shared(Q4);

    // ---- Stage: cp.async global -> batch-major smem ----
#pragma unroll
    for (int i = 0; i < 5; ++i) {               // positions: 18 f4/batch
        int f = i * NT + tid;
        if (f < nfp) {
            int b = f / 18, k = f - b * 18;
            cp16(sA + (unsigned int)(b * (AS / 4) + k) * 16u, &gp4[f]);
        }
    }
#pragma unroll
    for (int i = 0; i < 6; ++i) {               // quats: 24 f4/batch, skip leaves
        int f = i * NT + tid;
        if (f < nfq) {
            int b = f / 24, j = f - b * 24;
            if ((QMASK >> j) & 1u) {
                cp16(sQ + (unsigned int)(b * (QS / 4) + j) * 16u, &gq4[f]);
            }
        }
    }
    asm volatile("cp.async.commit_group;\n" ::: "memory");
    asm volatile("cp.async.wait_group 0;\n" ::: "memory");
    __syncthreads();

    // ---- Compute: 4 lanes per batch, parallel chains in lockstep ----
    const bool ok = FULL || (col < nb);
    const float* Ab = A + col * AS;
    float* Aw = A + col * AS;
    const float4* Qb = Q4 + col * (QS / 4);

    auto localcompose = [&](const G& a, int j) -> G {
        float4 q = Qb[j];                        // one LDS.128, bank-rotated
        return compose(a, q, Ab[3 * j + 0], Ab[3 * j + 1], Ab[3 * j + 2]);
    };
    auto putx = [&](int j, const G& g) {
        Aw[3 * j + 0] = g.tx;
        Aw[3 * j + 1] = g.ty;
        Aw[3 * j + 2] = g.tz;
    };
    auto putleaf = [&](int j, const G& a) {
        float ox, oy, oz;
        rot_point(a, Ab[3 * j + 0], Ab[3 * j + 1], Ab[3 * j + 2], ox, oy, oz);
        Aw[3 * j + 0] = ox;
        Aw[3 * j + 1] = oy;
        Aw[3 * j + 2] = oz;
    };

    // Root (quad lanes read identical addresses -> smem broadcast).
    G g;
    {
        float4 q0 = Qb[0];
        g.qw = q0.x; g.qx = q0.y; g.qy = q0.z; g.qz = q0.w;
        float n0 = g.qw * g.qw + g.qx * g.qx + g.qy * g.qy + g.qz * g.qz;
        g.s = __fdividef(2.0f, n0);
        g.tx = Ab[0]; g.ty = Ab[1]; g.tz = Ab[2];
    }
    // out joint 0 == pos 0: already resident in A words 0..2.

    // Phase 1: chains {1,4,7} / {2,5,8} / {3,6,9} (sub3 duplicates sub2).
    const int s2 = (sub < 2) ? sub : 2;
#pragma unroll
    for (int k = 0; k < 3; ++k) {
        int j = 3 * k + 1 + s2;
        g = localcompose(g, j);
        if (ok && sub != 3) putx(j, g);
    }
    if (ok && sub < 2) putleaf(10 + sub, g);     // leaves 10, 11

    // Broadcast g9 from the quad's sub2 lane.
    {
        int src = (lane & ~3) | 2;
        G h;
        h.qw = shfl_from(g.qw, src); h.qx = shfl_from(g.qx, src);
        h.qy = shfl_from(g.qy, src); h.qz = shfl_from(g.qz, src);
        h.tx = shfl_from(g.tx, src); h.ty = shfl_from(g.ty, src);
        h.tz = shfl_from(g.tz, src); h.s  = shfl_from(g.s,  src);
        g = h;
    }

    // Phase 2: sub0: 12 -> leaf15; sub1: 13,16,18,20 -> leaf22;
    //          sub2: 14,17,19,21 -> leaf23; sub3 idle.
    if (sub < 3) {
        int j = 12 + sub;
        g = localcompose(g, j);
        if (ok) putx(j, g);
    }
#pragma unroll
    for (int k = 1; k < 4; ++k) {
        if (sub == 1 || sub == 2) {
            int j = 13 + 2 * k + sub;            // 16/17, 18/19, 20/21
            g = localcompose(g, j);
            if (ok) putx(j, g);
        }
    }
    {
        int lj = (sub == 0) ? 15 : (sub == 1) ? 22 : (sub == 2) ? 23 : -1;
        if (ok && lj >= 0) putleaf(lj, g);
    }

    __syncthreads();

    // ---- Flush: batch-major smem -> coalesced global (vector loads) ----
#pragma unroll
    for (int i = 0; i < 5; ++i) {
        int f = i * NT + tid;
        if (f < nfp) {
            int b = f / 18, k = f - b * 18;
            go4[f] = A4[b * (AS / 4) + k];
        }
    }
}

extern "C" void kernel_launch(void* const* d_in, const int* in_sizes, int n_in,
                              void* d_out, int out_size) {
    // metadata order: parents (int64, unused — tree is compile-time),
    //                 positions (B*24*3 f32), rotations (B*24*4 f32)
    const float* pos = (const float*)d_in[1];
    const float* rot = (const float*)d_in[2];
    float* out = (float*)d_out;

    int B = in_sizes[1] / 72;
    int grid = (B + NB - 1) / NB;
    if (B % NB == 0)
        fk_kernel<true><<<grid, NT>>>(pos, rot, out, B);
    else
        fk_kernel<false><<<grid, NT>>>(pos, rot, out, B);
}